// round 1
// baseline (speedup 1.0000x reference)
#include <cuda_runtime.h>
#include <math.h>

#define B_    8
#define N_    4096
#define CIN   256
#define CQK   32
#define NROWS (B_ * N_)   // 32768

// ---- scratch (device globals; no allocation allowed) ----
__device__ float g_q[NROWS * CQK];     // 4 MB
__device__ float g_k[NROWS * CQK];     // 4 MB
__device__ float g_vbar[NROWS];
__device__ float g_xbar[NROWS];
__device__ float g_wvbar[CIN];
__device__ float g_bvbar;

// ---------------------------------------------------------------------------
// Kernel 0: wv_bar[i] = mean_j Wv[i,j];  bvbar = mean(bv)
// ---------------------------------------------------------------------------
__global__ void prep_kernel(const float* __restrict__ Wv,
                            const float* __restrict__ bv) {
    int i = threadIdx.x;          // 256 threads
    float s = 0.f;
    #pragma unroll 4
    for (int j = 0; j < CIN; j++) s += Wv[i * CIN + j];
    g_wvbar[i] = s * (1.f / CIN);
    if (i == 0) {
        float t = 0.f;
        for (int j = 0; j < CIN; j++) t += bv[j];
        g_bvbar = t * (1.f / CIN);
    }
}

// ---------------------------------------------------------------------------
// Kernel 1: fused Q/K projection GEMM.
//   C(32768 x 64) = x(32768 x 256) @ [Wq | Wk](256 x 64), + bias, split-stored.
//   Tile: 128 x 64, K-tile 32. 256 threads (16x16), each 8x4 micro-tile.
// ---------------------------------------------------------------------------
__global__ __launch_bounds__(256) void qk_gemm(
    const float* __restrict__ x,
    const float* __restrict__ Wq, const float* __restrict__ bq,
    const float* __restrict__ Wk, const float* __restrict__ bk) {

    __shared__ __align__(16) float As[128][36];  // padded vs 32 to break bank patterns
    __shared__ __align__(16) float Bs[32][64];

    const int tid = threadIdx.x;
    const int tx = tid & 15, ty = tid >> 4;
    const int m0 = blockIdx.x * 128;

    float acc[8][4];
    #pragma unroll
    for (int i = 0; i < 8; i++)
        #pragma unroll
        for (int j = 0; j < 4; j++) acc[i][j] = 0.f;

    for (int kt = 0; kt < CIN; kt += 32) {
        // load A tile: 128 rows x 32 cols of x
        {
            int c4 = tid & 7;        // float4 column
            int r0 = tid >> 3;       // 0..31
            #pragma unroll
            for (int p = 0; p < 4; p++) {
                int r = r0 + p * 32;
                float4 v = *(const float4*)(x + (size_t)(m0 + r) * CIN + kt + c4 * 4);
                *(float4*)(&As[r][c4 * 4]) = v;
            }
        }
        // load B tile: 32 rows x 64 cols ([Wq | Wk])
        {
            int c4 = tid & 15;       // 0..15
            int r0 = tid >> 4;       // 0..15
            #pragma unroll
            for (int p = 0; p < 2; p++) {
                int r = r0 + p * 16;
                float4 v;
                if (c4 < 8) v = *(const float4*)(Wq + (size_t)(kt + r) * CQK + c4 * 4);
                else        v = *(const float4*)(Wk + (size_t)(kt + r) * CQK + (c4 - 8) * 4);
                *(float4*)(&Bs[r][c4 * 4]) = v;
            }
        }
        __syncthreads();

        #pragma unroll
        for (int kk = 0; kk < 32; kk++) {
            float a[8];
            #pragma unroll
            for (int i = 0; i < 8; i++) a[i] = As[ty * 8 + i][kk];  // 2-addr broadcast
            float4 bv4 = *(const float4*)(&Bs[kk][tx * 4]);
            #pragma unroll
            for (int i = 0; i < 8; i++) {
                acc[i][0] += a[i] * bv4.x;
                acc[i][1] += a[i] * bv4.y;
                acc[i][2] += a[i] * bv4.z;
                acc[i][3] += a[i] * bv4.w;
            }
        }
        __syncthreads();
    }

    // epilogue: cols tx*4..+3; tx<8 -> Q, else K. Add bias, store float4.
    const int c = tx * 4;
    float4 bb;
    float* obase;
    int oc;
    if (c < 32) { bb = *(const float4*)(bq + c);      obase = g_q; oc = c; }
    else        { bb = *(const float4*)(bk + c - 32); obase = g_k; oc = c - 32; }
    #pragma unroll
    for (int i = 0; i < 8; i++) {
        int r = m0 + ty * 8 + i;
        float4 o;
        o.x = acc[i][0] + bb.x;
        o.y = acc[i][1] + bb.y;
        o.z = acc[i][2] + bb.z;
        o.w = acc[i][3] + bb.w;
        *(float4*)(obase + (size_t)r * CQK + oc) = o;
    }
}

// ---------------------------------------------------------------------------
// Kernel 2: per-row vbar / xbar (streaming pass over x). One warp per row.
// ---------------------------------------------------------------------------
__global__ __launch_bounds__(256) void vx_kernel(const float* __restrict__ x) {
    const int warp = threadIdx.x >> 5, lane = threadIdx.x & 31;
    const size_t row = (size_t)blockIdx.x * 8 + warp;   // 0..32767
    const float* xr = x + row * CIN;
    float sv = 0.f, sx = 0.f;
    #pragma unroll
    for (int j = 0; j < 8; j++) {
        float xv = xr[lane + j * 32];
        sv += xv * g_wvbar[lane + j * 32];
        sx += xv;
    }
    #pragma unroll
    for (int off = 16; off > 0; off >>= 1) {
        sv += __shfl_xor_sync(0xffffffffu, sv, off);
        sx += __shfl_xor_sync(0xffffffffu, sx, off);
    }
    if (lane == 0) {
        g_vbar[row] = sv + g_bvbar;
        g_xbar[row] = sx * (1.f / CIN);
    }
}

// ---------------------------------------------------------------------------
// Kernel 3: fused flash-style attention over the collapsed value scalar.
//   For query tile of 64 rows (one batch), stream all K in 128-col chunks.
//   energy[n,m] = q[n] . k[m]  (C_QK=32);  online softmax with scalar value
//   vbar[m]; final: out = gamma * num/den + xbar.
//   Block: 256 threads (16x16). ty owns 4 q-rows; tx strides m-columns.
// ---------------------------------------------------------------------------
__global__ __launch_bounds__(256) void attn_kernel(
    const float* __restrict__ gamma, float* __restrict__ out) {

    __shared__ __align__(16) float q_s[64][36];
    __shared__ __align__(16) float k_s[128][36];
    __shared__ float vb_s[128];

    const int b  = blockIdx.y;
    const int n0 = blockIdx.x * 64;
    const int tid = threadIdx.x;
    const int tx = tid & 15, ty = tid >> 4;

    // load q tile (64 x 32)
    {
        const float* qb = g_q + ((size_t)b * N_ + n0) * CQK;
        int c4 = tid & 7, r0 = tid >> 3;
        #pragma unroll
        for (int p = 0; p < 2; p++) {
            int r = r0 + p * 32;
            *(float4*)(&q_s[r][c4 * 4]) = *(const float4*)(qb + (size_t)r * CQK + c4 * 4);
        }
    }

    float mx[4], den[4], num[4];
    #pragma unroll
    for (int i = 0; i < 4; i++) { mx[i] = -1e30f; den[i] = 0.f; num[i] = 0.f; }

    for (int mc = 0; mc < N_; mc += 128) {
        __syncthreads();  // protect k_s / vb_s from previous iteration readers; orders q_s on iter 0
        {
            const float* kb = g_k + ((size_t)b * N_ + mc) * CQK;
            int c4 = tid & 7, r0 = tid >> 3;
            #pragma unroll
            for (int p = 0; p < 4; p++) {
                int r = r0 + p * 32;
                *(float4*)(&k_s[r][c4 * 4]) = *(const float4*)(kb + (size_t)r * CQK + c4 * 4);
            }
            if (tid < 128) vb_s[tid] = g_vbar[(size_t)b * N_ + mc + tid];
        }
        __syncthreads();

        float acc[4][8];
        #pragma unroll
        for (int i = 0; i < 4; i++)
            #pragma unroll
            for (int j = 0; j < 8; j++) acc[i][j] = 0.f;

        #pragma unroll
        for (int c4 = 0; c4 < 8; c4++) {
            float4 qv[4];
            #pragma unroll
            for (int i = 0; i < 4; i++)
                qv[i] = *(const float4*)(&q_s[ty * 4 + i][c4 * 4]);
            #pragma unroll
            for (int j = 0; j < 8; j++) {
                float4 kv = *(const float4*)(&k_s[tx + 16 * j][c4 * 4]);
                #pragma unroll
                for (int i = 0; i < 4; i++) {
                    acc[i][j] += qv[i].x * kv.x;
                    acc[i][j] += qv[i].y * kv.y;
                    acc[i][j] += qv[i].z * kv.z;
                    acc[i][j] += qv[i].w * kv.w;
                }
            }
        }

        // online softmax update (per thread over its 8 columns)
        #pragma unroll
        for (int i = 0; i < 4; i++) {
            float cm = acc[i][0];
            #pragma unroll
            for (int j = 1; j < 8; j++) cm = fmaxf(cm, acc[i][j]);
            if (cm > mx[i]) {
                float f = __expf(mx[i] - cm);
                den[i] *= f; num[i] *= f; mx[i] = cm;
            }
            #pragma unroll
            for (int j = 0; j < 8; j++) {
                float e = __expf(acc[i][j] - mx[i]);
                den[i] += e;
                num[i] += e * vb_s[tx + 16 * j];
            }
        }
    }

    // merge across the 16 lanes sharing each q-row (same ty == same half-warp)
    const float g = gamma[0];
    #pragma unroll
    for (int i = 0; i < 4; i++) {
        float mi = mx[i], si = den[i], ni = num[i];
        #pragma unroll
        for (int off = 1; off < 16; off <<= 1) {
            float om = __shfl_xor_sync(0xffffffffu, mi, off);
            float os = __shfl_xor_sync(0xffffffffu, si, off);
            float on = __shfl_xor_sync(0xffffffffu, ni, off);
            float nm = fmaxf(mi, om);
            float fa = __expf(mi - nm);
            float fb = __expf(om - nm);
            si = si * fa + os * fb;
            ni = ni * fa + on * fb;
            mi = nm;
        }
        if (tx == 0) {
            int row = n0 + ty * 4 + i;
            size_t idx = (size_t)b * N_ + row;
            out[idx] = g * (ni / si) + g_xbar[idx];
        }
    }
}

// ---------------------------------------------------------------------------
extern "C" void kernel_launch(void* const* d_in, const int* in_sizes, int n_in,
                              void* d_out, int out_size) {
    const float* x     = (const float*)d_in[0];
    const float* Wq    = (const float*)d_in[1];
    const float* bq    = (const float*)d_in[2];
    const float* Wk    = (const float*)d_in[3];
    const float* bk    = (const float*)d_in[4];
    const float* Wv    = (const float*)d_in[5];
    const float* bv    = (const float*)d_in[6];
    const float* gamma = (const float*)d_in[7];
    float* out = (float*)d_out;

    prep_kernel<<<1, 256>>>(Wv, bv);
    qk_gemm<<<NROWS / 128, 256>>>(x, Wq, bq, Wk, bk);
    vx_kernel<<<NROWS / 8, 256>>>(x);
    attn_kernel<<<dim3(N_ / 64, B_), 256>>>(gamma, out);
}